// round 6
// baseline (speedup 1.0000x reference)
#include <cuda_runtime.h>
#include <cuda_bf16.h>
#include <cstdint>

#define KS   5
#define K2   25
#define C1   32
#define C2   64
#define NG   64
#define NMAX 20000
#define KTOT 800

// ---------------- scratch (device globals; no allocations) ----------------
__device__ float        g_T[NMAX * K2];
__device__ float        g_deg[NMAX];
__device__ float        g_dinv[NMAX];
__device__ unsigned int g_h1b[NMAX * 16];     // h1 bf16x2 packed [N][16]
__device__ unsigned int g_Sb[NMAX * 400];     // S accum bf16x2 [N][25][16] (32MB)
__device__ uint2        g_W2f[56 * 8 * 32];   // B fragments: [kstep][ngroup][lane] (+root2 at 52-53)
__device__ float        g_pool[NG * C2];

// ---------------- helpers ----------------
__device__ __forceinline__ uint32_t smem_u32(const void* p) {
    uint32_t a;
    asm("{ .reg .u64 t; cvta.to.shared.u64 t, %1; cvt.u32.u64 %0, t; }" : "=r"(a) : "l"(p));
    return a;
}
__device__ __forceinline__ void red_f32(float* addr, float v) {
    asm volatile("red.global.add.f32 [%0], %1;" :: "l"(addr), "f"(v) : "memory");
}
__device__ __forceinline__ void red_v2f32(float* addr, float a, float b) {
    asm volatile("red.global.add.v2.f32 [%0], {%1, %2};"
                 :: "l"(addr), "f"(a), "f"(b) : "memory");
}
__device__ __forceinline__ void red_v4bf162(unsigned int* addr, uint32_t a, uint32_t b,
                                            uint32_t c, uint32_t d) {
    asm volatile("red.global.add.noftz.v4.bf16x2 [%0], {%1, %2, %3, %4};"
                 :: "l"(addr), "r"(a), "r"(b), "r"(c), "r"(d) : "memory");
}
__device__ __forceinline__ uint32_t scale_bf162(uint32_t v, float s) {
    float2 f = __bfloat1622float2(*(__nv_bfloat162*)&v);
    __nv_bfloat162 r = __float22bfloat162_rn(make_float2(f.x * s, f.y * s));
    return *(uint32_t*)&r;
}
__device__ __forceinline__ void ldmatrix_x4(uint32_t& a0, uint32_t& a1, uint32_t& a2,
                                            uint32_t& a3, uint32_t addr) {
    asm volatile("ldmatrix.sync.aligned.m8n8.x4.shared.b16 {%0,%1,%2,%3}, [%4];"
                 : "=r"(a0), "=r"(a1), "=r"(a2), "=r"(a3) : "r"(addr));
}
__device__ __forceinline__ void mma_bf16(float* c, uint32_t a0, uint32_t a1, uint32_t a2,
                                         uint32_t a3, uint32_t b0, uint32_t b1) {
    asm volatile(
        "mma.sync.aligned.m16n8k16.row.col.f32.bf16.bf16.f32 "
        "{%0,%1,%2,%3}, {%4,%5,%6,%7}, {%8,%9}, {%0,%1,%2,%3};"
        : "+f"(c[0]), "+f"(c[1]), "+f"(c[2]), "+f"(c[3])
        : "r"(a0), "r"(a1), "r"(a2), "r"(a3), "r"(b0), "r"(b1));
}

// ---------------- basis ----------------
__device__ __forceinline__ void basis2(float a0, float a1, int* wi, float* bw) {
    float v0 = a0 * (KS - 1), v1 = a1 * (KS - 1);
    int k0 = (int)floorf(v0); k0 = min(max(k0, 0), KS - 2);
    int k1 = (int)floorf(v1); k1 = min(max(k1, 0), KS - 2);
    float f0 = v0 - (float)k0, f1 = v1 - (float)k1;
    float g0 = 1.f - f0, g1 = 1.f - f1;
    wi[0] = k0     + KS *  k1;      bw[0] = g0 * g1;
    wi[1] = k0 + 1 + KS *  k1;      bw[1] = f0 * g1;
    wi[2] = k0     + KS * (k1 + 1); bw[2] = g0 * f1;
    wi[3] = k0 + 1 + KS * (k1 + 1); bw[3] = f0 * f1;
}

// ---------------- zero scratch + prep B fragments (fused) ----------------
__global__ void k_zero_prep(const float* __restrict__ W2, const float* __restrict__ root2,
                            int N) {
    long tid = (long)blockIdx.x * blockDim.x + threadIdx.x;
    long stride = (long)gridDim.x * blockDim.x;
    long nS4 = (long)N * 100;
    uint4* S4 = (uint4*)g_Sb;
    uint4 z4 = make_uint4(0u, 0u, 0u, 0u);
    for (long i = tid; i < nS4; i += stride) S4[i] = z4;
    long nT = (long)N * K2;
    for (long i = tid; i < nT; i += stride) g_T[i] = 0.f;
    for (long i = tid; i < N; i += stride) g_deg[i] = 0.f;
    for (long i = tid; i < NG * C2; i += stride) g_pool[i] = 0.f;
    // prep B fragments: first 56 blocks (14336 threads)
    if (tid < 56 * 8 * 32) {
        int t = (int)tid;
        int lane = t & 31, ng = (t >> 5) & 7, sg = t >> 8;
        int gid = lane >> 2, tig = lane & 3;
        int n = ng * 8 + gid;
        int k = sg * 16 + tig * 2;
        float f0 = 0.f, f1 = 0.f, f2 = 0.f, f3 = 0.f;
        if (sg < 50) {
            f0 = W2[k * C2 + n];       f1 = W2[(k + 1) * C2 + n];
            f2 = W2[(k + 8) * C2 + n]; f3 = W2[(k + 9) * C2 + n];
        } else if (sg >= 52 && sg < 54) {
            int kr = k - 832;
            f0 = root2[kr * C2 + n];       f1 = root2[(kr + 1) * C2 + n];
            f2 = root2[(kr + 8) * C2 + n]; f3 = root2[(kr + 9) * C2 + n];
        }
        __nv_bfloat162 lo = __float22bfloat162_rn(make_float2(f0, f1));
        __nv_bfloat162 hi = __float22bfloat162_rn(make_float2(f2, f3));
        g_W2f[t] = make_uint2(*(uint32_t*)&lo, *(uint32_t*)&hi);
    }
}

// ---------------- edge pass 1 ----------------
__global__ void k_edge1(const float* __restrict__ x, const float* __restrict__ ea,
                        const int* __restrict__ src, const int* __restrict__ dst, int E) {
    int e = blockIdx.x * blockDim.x + threadIdx.x;
    if (e >= E) return;
    int wi[4]; float bw[4];
    float2 eav = ((const float2*)ea)[e];
    basis2(eav.x, eav.y, wi, bw);
    float xs = x[src[e]];
    int d = dst[e];
    float* Tp = g_T + d * K2;
#pragma unroll
    for (int i = 0; i < 4; i++) red_f32(Tp + wi[i], bw[i] * xs);
    red_f32(g_deg + d, 1.f);
}

// ---------------- layer-1 node update: warp per node (atomic-free) ----------------
__global__ void __launch_bounds__(256) k_h1(const float* __restrict__ x,
                                            const float* __restrict__ W1,
                                            const float* __restrict__ root1,
                                            const float* __restrict__ b1, int N) {
    __shared__ float W1s[K2 * C1];
    __shared__ float root1s[C1], b1s[C1];
    int tid = threadIdx.x;
    for (int i = tid; i < K2 * C1; i += 256) W1s[i] = W1[i];
    if (tid < C1) { root1s[tid] = root1[tid]; b1s[tid] = b1[tid]; }
    __syncthreads();

    int warp = tid >> 5, lane = tid & 31;
    int n = blockIdx.x * 8 + warp;
    if (n >= N) return;

    float tval = (lane < K2) ? g_T[n * K2 + lane] : 0.f;
    float acc = 0.f;
#pragma unroll
    for (int w = 0; w < K2; w++)
        acc += __shfl_sync(0xffffffffu, tval, w) * W1s[w * C1 + lane];

    float dinv = 1.f / fmaxf(g_deg[n], 1.f);
    float xn = x[n];
    float h = fmaxf(acc * dinv + xn * root1s[lane] + b1s[lane], 0.f);
    float hother = __shfl_xor_sync(0xffffffffu, h, 1);
    if ((lane & 1) == 0) {
        __nv_bfloat162 hb = __float22bfloat162_rn(make_float2(h, hother));
        g_h1b[n * 16 + (lane >> 1)] = *(unsigned int*)&hb;
    }
    if (lane == 0) g_dinv[n] = dinv;
}

// ---------------- edge pass 2: v4.bf16x2 vector reds, 4 lanes/edge ----------------
__global__ void k_edge2(const float* __restrict__ ea,
                        const int* __restrict__ src, const int* __restrict__ dst, int E) {
    int gt = blockIdx.x * blockDim.x + threadIdx.x;
    int e = gt >> 2;            // 4 threads per edge
    int ql = gt & 3;            // quarter: channels [ql*8, ql*8+8)
    if (e >= E) return;
    int s = src[e], d = dst[e];
    float2 eav = ((const float2*)ea)[e];
    int wi[4]; float bw[4];
    basis2(eav.x, eav.y, wi, bw);
    uint4 h4 = *(const uint4*)(g_h1b + s * 16 + ql * 4);   // 8 channels bf16
    float2 h0 = __bfloat1622float2(*(__nv_bfloat162*)&h4.x);
    float2 h1 = __bfloat1622float2(*(__nv_bfloat162*)&h4.y);
    float2 h2 = __bfloat1622float2(*(__nv_bfloat162*)&h4.z);
    float2 h3 = __bfloat1622float2(*(__nv_bfloat162*)&h4.w);
    unsigned int* base = g_Sb + d * 400 + ql * 4;
#pragma unroll
    for (int i = 0; i < 4; i++) {
        float b = bw[i];
        __nv_bfloat162 v0 = __float22bfloat162_rn(make_float2(b * h0.x, b * h0.y));
        __nv_bfloat162 v1 = __float22bfloat162_rn(make_float2(b * h1.x, b * h1.y));
        __nv_bfloat162 v2 = __float22bfloat162_rn(make_float2(b * h2.x, b * h2.y));
        __nv_bfloat162 v3 = __float22bfloat162_rn(make_float2(b * h3.x, b * h3.y));
        red_v4bf162(base + wi[i] * 16,
                    *(uint32_t*)&v0, *(uint32_t*)&v1, *(uint32_t*)&v2, *(uint32_t*)&v3);
    }
}

// ---------------- fused GEMM (HMMA) + layer-2 epilogue + pooling ----------------
__global__ void __launch_bounds__(256) k_gemm_mma(const float* __restrict__ b2,
                                                  const int* __restrict__ batch, int N) {
    __shared__ __align__(16) uint8_t smA[16384];
    int tid = threadIdx.x;
    int warp = tid >> 5, lane = tid & 31;
    int gid = lane >> 2, tig = lane & 3;
    int rowBase = blockIdx.x * 128;
    uint32_t smA_b = smem_u32(smA);

    float acc[8][4];
#pragma unroll
    for (int g = 0; g < 8; g++)
#pragma unroll
        for (int j = 0; j < 4; j++) acc[g][j] = 0.f;

    for (int c0 = 0; c0 < 14; c0++) {
#pragma unroll
        for (int j = 0; j < 4; j++) {
            int c = tid + 256 * j;
            int row = c >> 3, ch = c & 7;
            int grow = rowBase + row;
            uint4 v = make_uint4(0u, 0u, 0u, 0u);
            if (grow < N) {
                if (c0 < 13) {
                    int off = c0 * 32 + ch * 4;
                    if (off < 400) {
                        v = *(const uint4*)(g_Sb + grow * 400 + off);
                        float s = g_dinv[grow];
                        v.x = scale_bf162(v.x, s); v.y = scale_bf162(v.y, s);
                        v.z = scale_bf162(v.z, s); v.w = scale_bf162(v.w, s);
                    }
                } else if (ch < 4) {
                    v = *(const uint4*)(g_h1b + grow * 16 + ch * 4);
                }
            }
            *(uint4*)(smA + row * 128 + ((ch ^ (row & 7)) << 4)) = v;
        }
        __syncthreads();
#pragma unroll
        for (int ks = 0; ks < 4; ks++) {
            int mrow = warp * 16 + (lane & 15);
            uint32_t addr = smA_b + mrow * 128 + (((ks * 2 + (lane >> 4)) ^ (mrow & 7)) << 4);
            uint32_t a0, a1, a2, a3;
            ldmatrix_x4(a0, a1, a2, a3, addr);
            int sg = c0 * 4 + ks;
            const uint2* bf = g_W2f + (sg << 8) + lane;
#pragma unroll
            for (int ng = 0; ng < 8; ng++) {
                uint2 b = bf[ng << 5];
                mma_bf16(acc[ng], a0, a1, a2, a3, b.x, b.y);
            }
        }
        __syncthreads();
    }

    int r0 = rowBase + warp * 16 + gid;
    int r1 = r0 + 8;
    int bt0 = (r0 < N) ? batch[r0] : -1;
    int bt1 = (r1 < N) ? batch[r1] : -1;
#pragma unroll
    for (int ng = 0; ng < 8; ng++) {
        int col = ng * 8 + tig * 2;
        float2 bb = *(const float2*)(b2 + col);
        if (bt0 >= 0)
            red_v2f32(g_pool + bt0 * C2 + col,
                      fmaxf(acc[ng][0] + bb.x, 0.f), fmaxf(acc[ng][1] + bb.y, 0.f));
        if (bt1 >= 0)
            red_v2f32(g_pool + bt1 * C2 + col,
                      fmaxf(acc[ng][2] + bb.x, 0.f), fmaxf(acc[ng][3] + bb.y, 0.f));
    }
}

// ---------------- head MLP + log_softmax (cnt via binary search on sorted batch) ----------------
__global__ void k_mlp(const float* __restrict__ Wf1, const float* __restrict__ bf1,
                      const float* __restrict__ Wf2, const float* __restrict__ bf2,
                      const int* __restrict__ batch, int N,
                      float* __restrict__ out) {
    int b = blockIdx.x;
    int j = threadIdx.x;
    __shared__ float gs[C2];
    __shared__ float ts[128];
    __shared__ float lg[10];
    __shared__ float s_cinv;
    if (j == 0) {
        // count nodes with batch == b (batch sorted ascending)
        int lo = 0, hi = N;
        while (lo < hi) { int m = (lo + hi) >> 1; if (batch[m] < b) lo = m + 1; else hi = m; }
        int lo2 = lo; hi = N;
        while (lo2 < hi) { int m = (lo2 + hi) >> 1; if (batch[m] < b + 1) lo2 = m + 1; else hi = m; }
        s_cinv = 1.f / fmaxf((float)(lo2 - lo), 1.f);
    }
    __syncthreads();
    if (j < C2) gs[j] = g_pool[b * C2 + j] * s_cinv;
    __syncthreads();
    float t = bf1[j];
#pragma unroll
    for (int k = 0; k < C2; k++) t += gs[k] * Wf1[k * 128 + j];
    ts[j] = fmaxf(t, 0.f);
    __syncthreads();
    if (j < 10) {
        float a = bf2[j];
#pragma unroll
        for (int q = 0; q < 128; q++) a += ts[q] * Wf2[q * 10 + j];
        lg[j] = a;
    }
    __syncthreads();
    if (j == 0) {
        float m = lg[0];
#pragma unroll
        for (int q = 1; q < 10; q++) m = fmaxf(m, lg[q]);
        float s = 0.f;
#pragma unroll
        for (int q = 0; q < 10; q++) s += expf(lg[q] - m);
        float l = logf(s) + m;
#pragma unroll
        for (int q = 0; q < 10; q++) out[b * 10 + q] = lg[q] - l;
    }
}

// ---------------- launch ----------------
extern "C" void kernel_launch(void* const* d_in, const int* in_sizes, int n_in,
                              void* d_out, int out_size) {
    const float* x     = (const float*)d_in[0];
    const float* ea    = (const float*)d_in[1];
    const float* W1    = (const float*)d_in[2];
    const float* root1 = (const float*)d_in[3];
    const float* b1    = (const float*)d_in[4];
    const float* W2    = (const float*)d_in[5];
    const float* root2 = (const float*)d_in[6];
    const float* b2    = (const float*)d_in[7];
    const float* Wf1   = (const float*)d_in[8];
    const float* bf1   = (const float*)d_in[9];
    const float* Wf2   = (const float*)d_in[10];
    const float* bf2   = (const float*)d_in[11];
    const int*   ei    = (const int*)d_in[12];
    const int*   batch = (const int*)d_in[13];

    int N = in_sizes[0];
    int E = in_sizes[1] / 2;
    const int* src = ei;
    const int* dst = ei + E;
    float* out = (float*)d_out;

    k_zero_prep<<<2048, 256>>>(W2, root2, N);
    k_edge1<<<(E + 255) / 256, 256>>>(x, ea, src, dst, E);
    k_h1<<<(N + 7) / 8, 256>>>(x, W1, root1, b1, N);
    k_edge2<<<(E * 4 + 255) / 256, 256>>>(ea, src, dst, E);
    k_gemm_mma<<<(N + 127) / 128, 256>>>(b2, batch, N);
    k_mlp<<<NG, 128>>>(Wf1, bf1, Wf2, bf2, batch, N, out);
}

// round 7
// speedup vs baseline: 1.2522x; 1.2522x over previous
#include <cuda_runtime.h>
#include <cuda_bf16.h>
#include <cstdint>

#define KS   5
#define K2   25
#define C1   32
#define C2   64
#define NG   64
#define NMAX 20000
#define KTOT 800

// ---------------- scratch (device globals; no allocations) ----------------
__device__ float        g_T[NMAX * K2];
__device__ float        g_deg[NMAX];
__device__ float        g_dinv[NMAX];
__device__ unsigned int g_h1b[NMAX * 16];     // h1 bf16x2 packed [N][16]
__device__ unsigned int g_Sb[NMAX * 400];     // S accum bf16x2 [N][25][16] (32MB)
__device__ uint2        g_W2f[56 * 8 * 32];   // B fragments: [kstep][ngroup][lane] (+root2 at 52-53)
__device__ float        g_pool[NG * C2];

// ---------------- helpers ----------------
__device__ __forceinline__ uint32_t smem_u32(const void* p) {
    uint32_t a;
    asm("{ .reg .u64 t; cvta.to.shared.u64 t, %1; cvt.u32.u64 %0, t; }" : "=r"(a) : "l"(p));
    return a;
}
__device__ __forceinline__ void red_bf162(unsigned int* addr, unsigned int v) {
    asm volatile("red.global.add.noftz.bf16x2 [%0], %1;" :: "l"(addr), "r"(v) : "memory");
}
__device__ __forceinline__ void red_f32(float* addr, float v) {
    asm volatile("red.global.add.f32 [%0], %1;" :: "l"(addr), "f"(v) : "memory");
}
__device__ __forceinline__ uint32_t scale_bf162(uint32_t v, float s) {
    float2 f = __bfloat1622float2(*(__nv_bfloat162*)&v);
    __nv_bfloat162 r = __float22bfloat162_rn(make_float2(f.x * s, f.y * s));
    return *(uint32_t*)&r;
}
__device__ __forceinline__ void ldmatrix_x4(uint32_t& a0, uint32_t& a1, uint32_t& a2,
                                            uint32_t& a3, uint32_t addr) {
    asm volatile("ldmatrix.sync.aligned.m8n8.x4.shared.b16 {%0,%1,%2,%3}, [%4];"
                 : "=r"(a0), "=r"(a1), "=r"(a2), "=r"(a3) : "r"(addr));
}
__device__ __forceinline__ void mma_bf16(float* c, uint32_t a0, uint32_t a1, uint32_t a2,
                                         uint32_t a3, uint32_t b0, uint32_t b1) {
    asm volatile(
        "mma.sync.aligned.m16n8k16.row.col.f32.bf16.bf16.f32 "
        "{%0,%1,%2,%3}, {%4,%5,%6,%7}, {%8,%9}, {%0,%1,%2,%3};"
        : "+f"(c[0]), "+f"(c[1]), "+f"(c[2]), "+f"(c[3])
        : "r"(a0), "r"(a1), "r"(a2), "r"(a3), "r"(b0), "r"(b1));
}

// ---------------- basis ----------------
__device__ __forceinline__ void basis2(float a0, float a1, int* wi, float* bw) {
    float v0 = a0 * (KS - 1), v1 = a1 * (KS - 1);
    int k0 = (int)floorf(v0); k0 = min(max(k0, 0), KS - 2);
    int k1 = (int)floorf(v1); k1 = min(max(k1, 0), KS - 2);
    float f0 = v0 - (float)k0, f1 = v1 - (float)k1;
    float g0 = 1.f - f0, g1 = 1.f - f1;
    wi[0] = k0     + KS *  k1;      bw[0] = g0 * g1;
    wi[1] = k0 + 1 + KS *  k1;      bw[1] = f0 * g1;
    wi[2] = k0     + KS * (k1 + 1); bw[2] = g0 * f1;
    wi[3] = k0 + 1 + KS * (k1 + 1); bw[3] = f0 * f1;
}

// ---------------- zero scratch + prep B fragments (fused) ----------------
__global__ void k_zero_prep(const float* __restrict__ W2, const float* __restrict__ root2,
                            int N) {
    long tid = (long)blockIdx.x * blockDim.x + threadIdx.x;
    long stride = (long)gridDim.x * blockDim.x;
    long nS4 = (long)N * 100;
    uint4* S4 = (uint4*)g_Sb;
    uint4 z4 = make_uint4(0u, 0u, 0u, 0u);
    for (long i = tid; i < nS4; i += stride) S4[i] = z4;
    long nT = (long)N * K2;
    for (long i = tid; i < nT; i += stride) g_T[i] = 0.f;
    for (long i = tid; i < N; i += stride) g_deg[i] = 0.f;
    for (long i = tid; i < NG * C2; i += stride) g_pool[i] = 0.f;
    if (tid < 56 * 8 * 32) {
        int t = (int)tid;
        int lane = t & 31, ng = (t >> 5) & 7, sg = t >> 8;
        int gid = lane >> 2, tig = lane & 3;
        int n = ng * 8 + gid;
        int k = sg * 16 + tig * 2;
        float f0 = 0.f, f1 = 0.f, f2 = 0.f, f3 = 0.f;
        if (sg < 50) {
            f0 = W2[k * C2 + n];       f1 = W2[(k + 1) * C2 + n];
            f2 = W2[(k + 8) * C2 + n]; f3 = W2[(k + 9) * C2 + n];
        } else if (sg >= 52 && sg < 54) {
            int kr = k - 832;
            f0 = root2[kr * C2 + n];       f1 = root2[(kr + 1) * C2 + n];
            f2 = root2[(kr + 8) * C2 + n]; f3 = root2[(kr + 9) * C2 + n];
        }
        __nv_bfloat162 lo = __float22bfloat162_rn(make_float2(f0, f1));
        __nv_bfloat162 hi = __float22bfloat162_rn(make_float2(f2, f3));
        g_W2f[t] = make_uint2(*(uint32_t*)&lo, *(uint32_t*)&hi);
    }
}

// ---------------- edge pass 1 ----------------
__global__ void k_edge1(const float* __restrict__ x, const float* __restrict__ ea,
                        const int* __restrict__ src, const int* __restrict__ dst, int E) {
    int e = blockIdx.x * blockDim.x + threadIdx.x;
    if (e >= E) return;
    int wi[4]; float bw[4];
    float2 eav = ((const float2*)ea)[e];
    basis2(eav.x, eav.y, wi, bw);
    float xs = x[src[e]];
    int d = dst[e];
    float* Tp = g_T + d * K2;
#pragma unroll
    for (int i = 0; i < 4; i++) atomicAdd(Tp + wi[i], bw[i] * xs);
    atomicAdd(g_deg + d, 1.f);
}

// ---------------- layer-1 node update (R4 per-thread form, atomic-free) ----------------
__global__ void k_h1(const float* __restrict__ x, const float* __restrict__ W1,
                     const float* __restrict__ root1, const float* __restrict__ b1, int N) {
    int t = blockIdx.x * blockDim.x + threadIdx.x;
    if (t >= N * 16) return;
    int n = t >> 4, c2 = t & 15;
    const float* Tp = g_T + n * K2;
    float a0 = 0.f, a1 = 0.f;
#pragma unroll
    for (int w = 0; w < K2; w++) {
        float tv = Tp[w];
        a0 += tv * W1[w * C1 + 2 * c2];
        a1 += tv * W1[w * C1 + 2 * c2 + 1];
    }
    float dinv = 1.f / fmaxf(g_deg[n], 1.f);
    float xn = x[n];
    float h0 = fmaxf(a0 * dinv + xn * root1[2 * c2]     + b1[2 * c2],     0.f);
    float h1 = fmaxf(a1 * dinv + xn * root1[2 * c2 + 1] + b1[2 * c2 + 1], 0.f);
    __nv_bfloat162 hb = __float22bfloat162_rn(make_float2(h0, h1));
    g_h1b[t] = *(unsigned int*)&hb;
    if (c2 == 0) g_dinv[n] = dinv;
}

// ---------------- edge pass 2: 16 lanes/edge, scalar bf16x2 red (proven best) ----------------
__global__ void k_edge2(const float* __restrict__ ea,
                        const int* __restrict__ src, const int* __restrict__ dst, int E) {
    int gt = blockIdx.x * blockDim.x + threadIdx.x;
    int lane = gt & 31;
    int warp = gt >> 5;
    int e = warp * 2 + (lane >> 4);
    int hl = lane & 15;
    if (e >= E) return;
    int s = src[e], d = dst[e];
    float2 eav = ((const float2*)ea)[e];
    int wi[4]; float bw[4];
    basis2(eav.x, eav.y, wi, bw);
    float2 h = __bfloat1622float2(*(__nv_bfloat162*)&g_h1b[s * 16 + hl]);
    unsigned int* base = g_Sb + d * 400 + hl;
#pragma unroll
    for (int i = 0; i < 4; i++) {
        __nv_bfloat162 v = __float22bfloat162_rn(make_float2(bw[i] * h.x, bw[i] * h.y));
        red_bf162(base + wi[i] * 16, *(unsigned int*)&v);
    }
}

// ---------------- fused GEMM (HMMA) + layer-2 epilogue + pooling ----------------
__global__ void __launch_bounds__(256) k_gemm_mma(const float* __restrict__ b2,
                                                  const int* __restrict__ batch, int N) {
    __shared__ __align__(16) uint8_t smA[16384];
    int tid = threadIdx.x;
    int warp = tid >> 5, lane = tid & 31;
    int gid = lane >> 2, tig = lane & 3;
    int rowBase = blockIdx.x * 128;
    uint32_t smA_b = smem_u32(smA);

    float acc[8][4];
#pragma unroll
    for (int g = 0; g < 8; g++)
#pragma unroll
        for (int j = 0; j < 4; j++) acc[g][j] = 0.f;

    for (int c0 = 0; c0 < 14; c0++) {
#pragma unroll
        for (int j = 0; j < 4; j++) {
            int c = tid + 256 * j;
            int row = c >> 3, ch = c & 7;
            int grow = rowBase + row;
            uint4 v = make_uint4(0u, 0u, 0u, 0u);
            if (grow < N) {
                if (c0 < 13) {
                    int off = c0 * 32 + ch * 4;
                    if (off < 400) {
                        v = *(const uint4*)(g_Sb + grow * 400 + off);
                        float s = g_dinv[grow];
                        v.x = scale_bf162(v.x, s); v.y = scale_bf162(v.y, s);
                        v.z = scale_bf162(v.z, s); v.w = scale_bf162(v.w, s);
                    }
                } else if (ch < 4) {
                    v = *(const uint4*)(g_h1b + grow * 16 + ch * 4);
                }
            }
            *(uint4*)(smA + row * 128 + ((ch ^ (row & 7)) << 4)) = v;
        }
        __syncthreads();
#pragma unroll
        for (int ks = 0; ks < 4; ks++) {
            int mrow = warp * 16 + (lane & 15);
            uint32_t addr = smA_b + mrow * 128 + (((ks * 2 + (lane >> 4)) ^ (mrow & 7)) << 4);
            uint32_t a0, a1, a2, a3;
            ldmatrix_x4(a0, a1, a2, a3, addr);
            int sg = c0 * 4 + ks;
            const uint2* bf = g_W2f + (sg << 8) + lane;
#pragma unroll
            for (int ng = 0; ng < 8; ng++) {
                uint2 b = bf[ng << 5];
                mma_bf16(acc[ng], a0, a1, a2, a3, b.x, b.y);
            }
        }
        __syncthreads();
    }

    int r0 = rowBase + warp * 16 + gid;
    int r1 = r0 + 8;
    int bt0 = (r0 < N) ? batch[r0] : -1;
    int bt1 = (r1 < N) ? batch[r1] : -1;
#pragma unroll
    for (int ng = 0; ng < 8; ng++) {
        int col = ng * 8 + tig * 2;
        float2 bb = *(const float2*)(b2 + col);
        if (bt0 >= 0) {
            red_f32(g_pool + bt0 * C2 + col,     fmaxf(acc[ng][0] + bb.x, 0.f));
            red_f32(g_pool + bt0 * C2 + col + 1, fmaxf(acc[ng][1] + bb.y, 0.f));
        }
        if (bt1 >= 0) {
            red_f32(g_pool + bt1 * C2 + col,     fmaxf(acc[ng][2] + bb.x, 0.f));
            red_f32(g_pool + bt1 * C2 + col + 1, fmaxf(acc[ng][3] + bb.y, 0.f));
        }
    }
}

// ---------------- head MLP + log_softmax (cnt via binary search on sorted batch) ----------------
__global__ void k_mlp(const float* __restrict__ Wf1, const float* __restrict__ bf1,
                      const float* __restrict__ Wf2, const float* __restrict__ bf2,
                      const int* __restrict__ batch, int N,
                      float* __restrict__ out) {
    int b = blockIdx.x;
    int j = threadIdx.x;
    __shared__ float gs[C2];
    __shared__ float ts[128];
    __shared__ float lg[10];
    __shared__ float s_cinv;
    if (j == 0) {
        int lo = 0, hi = N;
        while (lo < hi) { int m = (lo + hi) >> 1; if (batch[m] < b) lo = m + 1; else hi = m; }
        int lo2 = lo; hi = N;
        while (lo2 < hi) { int m = (lo2 + hi) >> 1; if (batch[m] < b + 1) lo2 = m + 1; else hi = m; }
        s_cinv = 1.f / fmaxf((float)(lo2 - lo), 1.f);
    }
    __syncthreads();
    if (j < C2) gs[j] = g_pool[b * C2 + j] * s_cinv;
    __syncthreads();
    float t = bf1[j];
#pragma unroll
    for (int k = 0; k < C2; k++) t += gs[k] * Wf1[k * 128 + j];
    ts[j] = fmaxf(t, 0.f);
    __syncthreads();
    if (j < 10) {
        float a = bf2[j];
#pragma unroll
        for (int q = 0; q < 128; q++) a += ts[q] * Wf2[q * 10 + j];
        lg[j] = a;
    }
    __syncthreads();
    if (j == 0) {
        float m = lg[0];
#pragma unroll
        for (int q = 1; q < 10; q++) m = fmaxf(m, lg[q]);
        float s = 0.f;
#pragma unroll
        for (int q = 0; q < 10; q++) s += expf(lg[q] - m);
        float l = logf(s) + m;
#pragma unroll
        for (int q = 0; q < 10; q++) out[b * 10 + q] = lg[q] - l;
    }
}

// ---------------- launch ----------------
extern "C" void kernel_launch(void* const* d_in, const int* in_sizes, int n_in,
                              void* d_out, int out_size) {
    const float* x     = (const float*)d_in[0];
    const float* ea    = (const float*)d_in[1];
    const float* W1    = (const float*)d_in[2];
    const float* root1 = (const float*)d_in[3];
    const float* b1    = (const float*)d_in[4];
    const float* W2    = (const float*)d_in[5];
    const float* root2 = (const float*)d_in[6];
    const float* b2    = (const float*)d_in[7];
    const float* Wf1   = (const float*)d_in[8];
    const float* bf1   = (const float*)d_in[9];
    const float* Wf2   = (const float*)d_in[10];
    const float* bf2   = (const float*)d_in[11];
    const int*   ei    = (const int*)d_in[12];
    const int*   batch = (const int*)d_in[13];

    int N = in_sizes[0];
    int E = in_sizes[1] / 2;
    const int* src = ei;
    const int* dst = ei + E;
    float* out = (float*)d_out;

    k_zero_prep<<<2048, 256>>>(W2, root2, N);
    k_edge1<<<(E + 255) / 256, 256>>>(x, ea, src, dst, E);
    k_h1<<<(N * 16 + 255) / 256, 256>>>(x, W1, root1, b1, N);
    k_edge2<<<(E * 16 + 255) / 256, 256>>>(ea, src, dst, E);
    k_gemm_mma<<<(N + 127) / 128, 256>>>(b2, batch, N);
    k_mlp<<<NG, 128>>>(Wf1, bf1, Wf2, bf2, batch, N, out);
}

// round 8
// speedup vs baseline: 1.5558x; 1.2425x over previous
#include <cuda_runtime.h>
#include <cuda_bf16.h>
#include <cstdint>

#define KS   5
#define K2   25
#define C1   32
#define C2   64
#define NG   64
#define NMAX 20000
#define KTOT 800

// ---------------- scratch (device globals; no allocations) ----------------
__device__ float        g_T[NMAX * K2];
__device__ float        g_deg[NMAX];
__device__ float        g_dinv[NMAX];
__device__ unsigned int g_h1b[NMAX * 16];     // h1 bf16x2 packed [N][16]
__device__ unsigned int g_Sb[NMAX * 400];     // S accum bf16x2 [N][25][16] (32MB), pre-scaled by dinv[dst]
__device__ uint2        g_W2f[56 * 8 * 32];   // B fragments: [kstep][ngroup][lane] (+root2 at 52-53)
__device__ float        g_pool[NG * C2];

// ---------------- helpers ----------------
__device__ __forceinline__ uint32_t smem_u32(const void* p) {
    uint32_t a;
    asm("{ .reg .u64 t; cvta.to.shared.u64 t, %1; cvt.u32.u64 %0, t; }" : "=r"(a) : "l"(p));
    return a;
}
__device__ __forceinline__ void red_bf162(unsigned int* addr, unsigned int v) {
    asm volatile("red.global.add.noftz.bf16x2 [%0], %1;" :: "l"(addr), "r"(v) : "memory");
}
__device__ __forceinline__ void red_f32(float* addr, float v) {
    asm volatile("red.global.add.f32 [%0], %1;" :: "l"(addr), "f"(v) : "memory");
}
__device__ __forceinline__ void ldmatrix_x4(uint32_t& a0, uint32_t& a1, uint32_t& a2,
                                            uint32_t& a3, uint32_t addr) {
    asm volatile("ldmatrix.sync.aligned.m8n8.x4.shared.b16 {%0,%1,%2,%3}, [%4];"
                 : "=r"(a0), "=r"(a1), "=r"(a2), "=r"(a3) : "r"(addr));
}
__device__ __forceinline__ void mma_bf16(float* c, uint32_t a0, uint32_t a1, uint32_t a2,
                                         uint32_t a3, uint32_t b0, uint32_t b1) {
    asm volatile(
        "mma.sync.aligned.m16n8k16.row.col.f32.bf16.bf16.f32 "
        "{%0,%1,%2,%3}, {%4,%5,%6,%7}, {%8,%9}, {%0,%1,%2,%3};"
        : "+f"(c[0]), "+f"(c[1]), "+f"(c[2]), "+f"(c[3])
        : "r"(a0), "r"(a1), "r"(a2), "r"(a3), "r"(b0), "r"(b1));
}

// ---------------- basis ----------------
__device__ __forceinline__ void basis2(float a0, float a1, int* wi, float* bw) {
    float v0 = a0 * (KS - 1), v1 = a1 * (KS - 1);
    int k0 = (int)floorf(v0); k0 = min(max(k0, 0), KS - 2);
    int k1 = (int)floorf(v1); k1 = min(max(k1, 0), KS - 2);
    float f0 = v0 - (float)k0, f1 = v1 - (float)k1;
    float g0 = 1.f - f0, g1 = 1.f - f1;
    wi[0] = k0     + KS *  k1;      bw[0] = g0 * g1;
    wi[1] = k0 + 1 + KS *  k1;      bw[1] = f0 * g1;
    wi[2] = k0     + KS * (k1 + 1); bw[2] = g0 * f1;
    wi[3] = k0 + 1 + KS * (k1 + 1); bw[3] = f0 * f1;
}

// ---------------- zero scratch + prep B fragments (fused) ----------------
__global__ void k_zero_prep(const float* __restrict__ W2, const float* __restrict__ root2,
                            int N) {
    long tid = (long)blockIdx.x * blockDim.x + threadIdx.x;
    long stride = (long)gridDim.x * blockDim.x;
    long nS4 = (long)N * 100;
    uint4* S4 = (uint4*)g_Sb;
    uint4 z4 = make_uint4(0u, 0u, 0u, 0u);
    for (long i = tid; i < nS4; i += stride) S4[i] = z4;
    long nT = (long)N * K2;
    for (long i = tid; i < nT; i += stride) g_T[i] = 0.f;
    for (long i = tid; i < N; i += stride) g_deg[i] = 0.f;
    for (long i = tid; i < NG * C2; i += stride) g_pool[i] = 0.f;
    if (tid < 56 * 8 * 32) {
        int t = (int)tid;
        int lane = t & 31, ng = (t >> 5) & 7, sg = t >> 8;
        int gid = lane >> 2, tig = lane & 3;
        int n = ng * 8 + gid;
        int k = sg * 16 + tig * 2;
        float f0 = 0.f, f1 = 0.f, f2 = 0.f, f3 = 0.f;
        if (sg < 50) {
            f0 = W2[k * C2 + n];       f1 = W2[(k + 1) * C2 + n];
            f2 = W2[(k + 8) * C2 + n]; f3 = W2[(k + 9) * C2 + n];
        } else if (sg >= 52 && sg < 54) {
            int kr = k - 832;
            f0 = root2[kr * C2 + n];       f1 = root2[(kr + 1) * C2 + n];
            f2 = root2[(kr + 8) * C2 + n]; f3 = root2[(kr + 9) * C2 + n];
        }
        __nv_bfloat162 lo = __float22bfloat162_rn(make_float2(f0, f1));
        __nv_bfloat162 hi = __float22bfloat162_rn(make_float2(f2, f3));
        g_W2f[t] = make_uint2(*(uint32_t*)&lo, *(uint32_t*)&hi);
    }
}

// ---------------- edge pass 1 ----------------
__global__ void k_edge1(const float* __restrict__ x, const float* __restrict__ ea,
                        const int* __restrict__ src, const int* __restrict__ dst, int E) {
    int e = blockIdx.x * blockDim.x + threadIdx.x;
    if (e >= E) return;
    int wi[4]; float bw[4];
    float2 eav = ((const float2*)ea)[e];
    basis2(eav.x, eav.y, wi, bw);
    float xs = x[src[e]];
    int d = dst[e];
    float* Tp = g_T + d * K2;
#pragma unroll
    for (int i = 0; i < 4; i++) atomicAdd(Tp + wi[i], bw[i] * xs);
    atomicAdd(g_deg + d, 1.f);
}

// ---------------- layer-1 node update (per-thread form, atomic-free) ----------------
__global__ void k_h1(const float* __restrict__ x, const float* __restrict__ W1,
                     const float* __restrict__ root1, const float* __restrict__ b1, int N) {
    int t = blockIdx.x * blockDim.x + threadIdx.x;
    if (t >= N * 16) return;
    int n = t >> 4, c2 = t & 15;
    const float* Tp = g_T + n * K2;
    float a0 = 0.f, a1 = 0.f;
#pragma unroll
    for (int w = 0; w < K2; w++) {
        float tv = Tp[w];
        a0 += tv * W1[w * C1 + 2 * c2];
        a1 += tv * W1[w * C1 + 2 * c2 + 1];
    }
    float dinv = 1.f / fmaxf(g_deg[n], 1.f);
    float xn = x[n];
    float h0 = fmaxf(a0 * dinv + xn * root1[2 * c2]     + b1[2 * c2],     0.f);
    float h1 = fmaxf(a1 * dinv + xn * root1[2 * c2 + 1] + b1[2 * c2 + 1], 0.f);
    __nv_bfloat162 hb = __float22bfloat162_rn(make_float2(h0, h1));
    g_h1b[t] = *(unsigned int*)&hb;
    if (c2 == 0) g_dinv[n] = dinv;
}

// ---------------- edge pass 2: 16 lanes/edge, scalar bf16x2 red; dinv[dst] folded in ----------------
__global__ void k_edge2(const float* __restrict__ ea,
                        const int* __restrict__ src, const int* __restrict__ dst, int E) {
    int gt = blockIdx.x * blockDim.x + threadIdx.x;
    int lane = gt & 31;
    int warp = gt >> 5;
    int e = warp * 2 + (lane >> 4);
    int hl = lane & 15;
    if (e >= E) return;
    int s = src[e], d = dst[e];
    float2 eav = ((const float2*)ea)[e];
    int wi[4]; float bw[4];
    basis2(eav.x, eav.y, wi, bw);
    float dinv = g_dinv[d];                      // fold mean-normalization into the message
    float2 h = __bfloat1622float2(*(__nv_bfloat162*)&g_h1b[s * 16 + hl]);
    h.x *= dinv; h.y *= dinv;
    unsigned int* base = g_Sb + d * 400 + hl;
#pragma unroll
    for (int i = 0; i < 4; i++) {
        __nv_bfloat162 v = __float22bfloat162_rn(make_float2(bw[i] * h.x, bw[i] * h.y));
        red_bf162(base + wi[i] * 16, *(unsigned int*)&v);
    }
}

// ---------------- fused GEMM (HMMA) + layer-2 epilogue + pooling ----------------
// A-fill is now a pure swizzled copy: S is already degree-normalized.
__global__ void __launch_bounds__(256) k_gemm_mma(const float* __restrict__ b2,
                                                  const int* __restrict__ batch, int N) {
    __shared__ __align__(16) uint8_t smA[16384];
    int tid = threadIdx.x;
    int warp = tid >> 5, lane = tid & 31;
    int gid = lane >> 2, tig = lane & 3;
    int rowBase = blockIdx.x * 128;
    uint32_t smA_b = smem_u32(smA);

    float acc[8][4];
#pragma unroll
    for (int g = 0; g < 8; g++)
#pragma unroll
        for (int j = 0; j < 4; j++) acc[g][j] = 0.f;

    for (int c0 = 0; c0 < 14; c0++) {
#pragma unroll
        for (int j = 0; j < 4; j++) {
            int c = tid + 256 * j;
            int row = c >> 3, ch = c & 7;
            int grow = rowBase + row;
            uint4 v = make_uint4(0u, 0u, 0u, 0u);
            if (grow < N) {
                if (c0 < 13) {
                    int off = c0 * 32 + ch * 4;
                    if (off < 400) v = *(const uint4*)(g_Sb + grow * 400 + off);
                } else if (ch < 4) {
                    v = *(const uint4*)(g_h1b + grow * 16 + ch * 4);
                }
            }
            *(uint4*)(smA + row * 128 + ((ch ^ (row & 7)) << 4)) = v;
        }
        __syncthreads();
#pragma unroll
        for (int ks = 0; ks < 4; ks++) {
            int mrow = warp * 16 + (lane & 15);
            uint32_t addr = smA_b + mrow * 128 + (((ks * 2 + (lane >> 4)) ^ (mrow & 7)) << 4);
            uint32_t a0, a1, a2, a3;
            ldmatrix_x4(a0, a1, a2, a3, addr);
            int sg = c0 * 4 + ks;
            const uint2* bf = g_W2f + (sg << 8) + lane;
#pragma unroll
            for (int ng = 0; ng < 8; ng++) {
                uint2 b = bf[ng << 5];
                mma_bf16(acc[ng], a0, a1, a2, a3, b.x, b.y);
            }
        }
        __syncthreads();
    }

    int r0 = rowBase + warp * 16 + gid;
    int r1 = r0 + 8;
    int bt0 = (r0 < N) ? batch[r0] : -1;
    int bt1 = (r1 < N) ? batch[r1] : -1;
#pragma unroll
    for (int ng = 0; ng < 8; ng++) {
        int col = ng * 8 + tig * 2;
        float2 bb = *(const float2*)(b2 + col);
        if (bt0 >= 0) {
            red_f32(g_pool + bt0 * C2 + col,     fmaxf(acc[ng][0] + bb.x, 0.f));
            red_f32(g_pool + bt0 * C2 + col + 1, fmaxf(acc[ng][1] + bb.y, 0.f));
        }
        if (bt1 >= 0) {
            red_f32(g_pool + bt1 * C2 + col,     fmaxf(acc[ng][2] + bb.x, 0.f));
            red_f32(g_pool + bt1 * C2 + col + 1, fmaxf(acc[ng][3] + bb.y, 0.f));
        }
    }
}

// ---------------- head MLP + log_softmax (cnt via binary search on sorted batch) ----------------
__global__ void k_mlp(const float* __restrict__ Wf1, const float* __restrict__ bf1,
                      const float* __restrict__ Wf2, const float* __restrict__ bf2,
                      const int* __restrict__ batch, int N,
                      float* __restrict__ out) {
    int b = blockIdx.x;
    int j = threadIdx.x;
    __shared__ float gs[C2];
    __shared__ float ts[128];
    __shared__ float lg[10];
    __shared__ float s_cinv;
    if (j == 0) {
        int lo = 0, hi = N;
        while (lo < hi) { int m = (lo + hi) >> 1; if (batch[m] < b) lo = m + 1; else hi = m; }
        int lo2 = lo; hi = N;
        while (lo2 < hi) { int m = (lo2 + hi) >> 1; if (batch[m] < b + 1) lo2 = m + 1; else hi = m; }
        s_cinv = 1.f / fmaxf((float)(lo2 - lo), 1.f);
    }
    __syncthreads();
    if (j < C2) gs[j] = g_pool[b * C2 + j] * s_cinv;
    __syncthreads();
    float t = bf1[j];
#pragma unroll
    for (int k = 0; k < C2; k++) t += gs[k] * Wf1[k * 128 + j];
    ts[j] = fmaxf(t, 0.f);
    __syncthreads();
    if (j < 10) {
        float a = bf2[j];
#pragma unroll
        for (int q = 0; q < 128; q++) a += ts[q] * Wf2[q * 10 + j];
        lg[j] = a;
    }
    __syncthreads();
    if (j == 0) {
        float m = lg[0];
#pragma unroll
        for (int q = 1; q < 10; q++) m = fmaxf(m, lg[q]);
        float s = 0.f;
#pragma unroll
        for (int q = 0; q < 10; q++) s += expf(lg[q] - m);
        float l = logf(s) + m;
#pragma unroll
        for (int q = 0; q < 10; q++) out[b * 10 + q] = lg[q] - l;
    }
}

// ---------------- launch ----------------
extern "C" void kernel_launch(void* const* d_in, const int* in_sizes, int n_in,
                              void* d_out, int out_size) {
    const float* x     = (const float*)d_in[0];
    const float* ea    = (const float*)d_in[1];
    const float* W1    = (const float*)d_in[2];
    const float* root1 = (const float*)d_in[3];
    const float* b1    = (const float*)d_in[4];
    const float* W2    = (const float*)d_in[5];
    const float* root2 = (const float*)d_in[6];
    const float* b2    = (const float*)d_in[7];
    const float* Wf1   = (const float*)d_in[8];
    const float* bf1   = (const float*)d_in[9];
    const float* Wf2   = (const float*)d_in[10];
    const float* bf2   = (const float*)d_in[11];
    const int*   ei    = (const int*)d_in[12];
    const int*   batch = (const int*)d_in[13];

    int N = in_sizes[0];
    int E = in_sizes[1] / 2;
    const int* src = ei;
    const int* dst = ei + E;
    float* out = (float*)d_out;

    k_zero_prep<<<2048, 256>>>(W2, root2, N);
    k_edge1<<<(E + 255) / 256, 256>>>(x, ea, src, dst, E);
    k_h1<<<(N * 16 + 255) / 256, 256>>>(x, W1, root1, b1, N);
    k_edge2<<<(E * 16 + 255) / 256, 256>>>(ea, src, dst, E);
    k_gemm_mma<<<(N + 127) / 128, 256>>>(b2, batch, N);
    k_mlp<<<NG, 128>>>(Wf1, bf1, Wf2, bf2, batch, N, out);
}

// round 10
// speedup vs baseline: 1.7009x; 1.0933x over previous
#include <cuda_runtime.h>
#include <cuda_bf16.h>
#include <cstdint>

#define KS   5
#define K2   25
#define C1   32
#define C2   64
#define NG   64
#define NMAX 20000
#define EMAX 320000
#define KTOT 800

// ---------------- scratch (device globals; no allocations) ----------------
__device__ float        g_T[NMAX * K2];
__device__ float        g_deg[NMAX];
__device__ float        g_dinv[NMAX];
__device__ unsigned int g_h1b[NMAX * 16];     // h1 bf16x2 packed [N][16]
__device__ unsigned int g_Sb[NMAX * 400];     // S accum bf16x2 [N][25][16] (32MB), pre-scaled by dinv[dst]
__device__ uint2        g_W2f[56 * 8 * 32];   // B fragments: [kstep][ngroup][lane] (+root2 at 52-53)
__device__ float        g_pool[NG * C2];
__device__ uint32_t     g_wip[EMAX];          // per-edge packed 4x u8 kernel indices
__device__ float4       g_bwp[EMAX];          // per-edge 4x fp32 basis weights

// ---------------- helpers ----------------
__device__ __forceinline__ uint32_t smem_u32(const void* p) {
    uint32_t a;
    asm("{ .reg .u64 t; cvta.to.shared.u64 t, %1; cvt.u32.u64 %0, t; }" : "=r"(a) : "l"(p));
    return a;
}
__device__ __forceinline__ void red_bf162(unsigned int* addr, unsigned int v) {
    asm volatile("red.global.add.noftz.bf16x2 [%0], %1;" :: "l"(addr), "r"(v) : "memory");
}
__device__ __forceinline__ void red_f32(float* addr, float v) {
    asm volatile("red.global.add.f32 [%0], %1;" :: "l"(addr), "f"(v) : "memory");
}
__device__ __forceinline__ void ldmatrix_x4(uint32_t& a0, uint32_t& a1, uint32_t& a2,
                                            uint32_t& a3, uint32_t addr) {
    asm volatile("ldmatrix.sync.aligned.m8n8.x4.shared.b16 {%0,%1,%2,%3}, [%4];"
                 : "=r"(a0), "=r"(a1), "=r"(a2), "=r"(a3) : "r"(addr));
}
__device__ __forceinline__ void mma_bf16(float* c, uint32_t a0, uint32_t a1, uint32_t a2,
                                         uint32_t a3, uint32_t b0, uint32_t b1) {
    asm volatile(
        "mma.sync.aligned.m16n8k16.row.col.f32.bf16.bf16.f32 "
        "{%0,%1,%2,%3}, {%4,%5,%6,%7}, {%8,%9}, {%0,%1,%2,%3};"
        : "+f"(c[0]), "+f"(c[1]), "+f"(c[2]), "+f"(c[3])
        : "r"(a0), "r"(a1), "r"(a2), "r"(a3), "r"(b0), "r"(b1));
}

// ---------------- basis ----------------
__device__ __forceinline__ void basis2(float a0, float a1, int* wi, float* bw) {
    float v0 = a0 * (KS - 1), v1 = a1 * (KS - 1);
    int k0 = (int)floorf(v0); k0 = min(max(k0, 0), KS - 2);
    int k1 = (int)floorf(v1); k1 = min(max(k1, 0), KS - 2);
    float f0 = v0 - (float)k0, f1 = v1 - (float)k1;
    float g0 = 1.f - f0, g1 = 1.f - f1;
    wi[0] = k0     + KS *  k1;      bw[0] = g0 * g1;
    wi[1] = k0 + 1 + KS *  k1;      bw[1] = f0 * g1;
    wi[2] = k0     + KS * (k1 + 1); bw[2] = g0 * f1;
    wi[3] = k0 + 1 + KS * (k1 + 1); bw[3] = f0 * f1;
}

// ---------------- zero scratch + prep B fragments (fused) ----------------
__global__ void k_zero_prep(const float* __restrict__ W2, const float* __restrict__ root2,
                            int N) {
    long tid = (long)blockIdx.x * blockDim.x + threadIdx.x;
    long stride = (long)gridDim.x * blockDim.x;
    long nS4 = (long)N * 100;
    uint4* S4 = (uint4*)g_Sb;
    uint4 z4 = make_uint4(0u, 0u, 0u, 0u);
    for (long i = tid; i < nS4; i += stride) S4[i] = z4;
    long nT = (long)N * K2;
    for (long i = tid; i < nT; i += stride) g_T[i] = 0.f;
    for (long i = tid; i < N; i += stride) g_deg[i] = 0.f;
    for (long i = tid; i < NG * C2; i += stride) g_pool[i] = 0.f;
    if (tid < 56 * 8 * 32) {
        int t = (int)tid;
        int lane = t & 31, ng = (t >> 5) & 7, sg = t >> 8;
        int gid = lane >> 2, tig = lane & 3;
        int n = ng * 8 + gid;
        int k = sg * 16 + tig * 2;
        float f0 = 0.f, f1 = 0.f, f2 = 0.f, f3 = 0.f;
        if (sg < 50) {
            f0 = W2[k * C2 + n];       f1 = W2[(k + 1) * C2 + n];
            f2 = W2[(k + 8) * C2 + n]; f3 = W2[(k + 9) * C2 + n];
        } else if (sg >= 52 && sg < 54) {
            int kr = k - 832;
            f0 = root2[kr * C2 + n];       f1 = root2[(kr + 1) * C2 + n];
            f2 = root2[(kr + 8) * C2 + n]; f3 = root2[(kr + 9) * C2 + n];
        }
        __nv_bfloat162 lo = __float22bfloat162_rn(make_float2(f0, f1));
        __nv_bfloat162 hi = __float22bfloat162_rn(make_float2(f2, f3));
        g_W2f[t] = make_uint2(*(uint32_t*)&lo, *(uint32_t*)&hi);
    }
}

// ---------------- edge pass 1 (also stores basis for edge2) ----------------
__global__ void k_edge1(const float* __restrict__ x, const float* __restrict__ ea,
                        const int* __restrict__ src, const int* __restrict__ dst, int E) {
    int e = blockIdx.x * blockDim.x + threadIdx.x;
    if (e >= E) return;
    int wi[4]; float bw[4];
    float2 eav = ((const float2*)ea)[e];
    basis2(eav.x, eav.y, wi, bw);
    float xs = x[src[e]];
    int d = dst[e];
    float* Tp = g_T + d * K2;
#pragma unroll
    for (int i = 0; i < 4; i++) atomicAdd(Tp + wi[i], bw[i] * xs);
    atomicAdd(g_deg + d, 1.f);
    g_wip[e] = (uint32_t)wi[0] | ((uint32_t)wi[1] << 8) |
               ((uint32_t)wi[2] << 16) | ((uint32_t)wi[3] << 24);
    g_bwp[e] = make_float4(bw[0], bw[1], bw[2], bw[3]);
}

// ---------------- layer-1 node update (per-thread form, atomic-free) ----------------
__global__ void k_h1(const float* __restrict__ x, const float* __restrict__ W1,
                     const float* __restrict__ root1, const float* __restrict__ b1, int N) {
    int t = blockIdx.x * blockDim.x + threadIdx.x;
    if (t >= N * 16) return;
    int n = t >> 4, c2 = t & 15;
    const float* Tp = g_T + n * K2;
    float a0 = 0.f, a1 = 0.f;
#pragma unroll
    for (int w = 0; w < K2; w++) {
        float tv = Tp[w];
        a0 += tv * W1[w * C1 + 2 * c2];
        a1 += tv * W1[w * C1 + 2 * c2 + 1];
    }
    float dinv = 1.f / fmaxf(g_deg[n], 1.f);
    float xn = x[n];
    float h0 = fmaxf(a0 * dinv + xn * root1[2 * c2]     + b1[2 * c2],     0.f);
    float h1 = fmaxf(a1 * dinv + xn * root1[2 * c2 + 1] + b1[2 * c2 + 1], 0.f);
    __nv_bfloat162 hb = __float22bfloat162_rn(make_float2(h0, h1));
    g_h1b[t] = *(unsigned int*)&hb;
    if (c2 == 0) g_dinv[n] = dinv;
}

// ---------------- edge pass 2: 16 lanes/edge, basis precomputed, dinv folded in ----------------
__global__ void k_edge2(const int* __restrict__ src, const int* __restrict__ dst, int E) {
    int gt = blockIdx.x * blockDim.x + threadIdx.x;
    int lane = gt & 31;
    int warp = gt >> 5;
    int e = warp * 2 + (lane >> 4);
    int hl = lane & 15;
    if (e >= E) return;
    int s = src[e], d = dst[e];
    uint32_t wip = g_wip[e];
    float4 bw = g_bwp[e];
    float dinv = g_dinv[d];
    float2 h = __bfloat1622float2(*(__nv_bfloat162*)&g_h1b[s * 16 + hl]);
    h.x *= dinv; h.y *= dinv;
    unsigned int* base = g_Sb + d * 400 + hl;
    {
        __nv_bfloat162 v = __float22bfloat162_rn(make_float2(bw.x * h.x, bw.x * h.y));
        red_bf162(base + (wip & 0xffu) * 16, *(unsigned int*)&v);
    }
    {
        __nv_bfloat162 v = __float22bfloat162_rn(make_float2(bw.y * h.x, bw.y * h.y));
        red_bf162(base + ((wip >> 8) & 0xffu) * 16, *(unsigned int*)&v);
    }
    {
        __nv_bfloat162 v = __float22bfloat162_rn(make_float2(bw.z * h.x, bw.z * h.y));
        red_bf162(base + ((wip >> 16) & 0xffu) * 16, *(unsigned int*)&v);
    }
    {
        __nv_bfloat162 v = __float22bfloat162_rn(make_float2(bw.w * h.x, bw.w * h.y));
        red_bf162(base + (wip >> 24) * 16, *(unsigned int*)&v);
    }
}

// ---------------- fused GEMM (HMMA) + layer-2 epilogue + pooling ----------------
// Software-pipelined A-fill: LDG of chunk c+1 overlaps MMA of chunk c.
__global__ void __launch_bounds__(256) k_gemm_mma(const float* __restrict__ b2,
                                                  const int* __restrict__ batch, int N) {
    __shared__ __align__(16) uint8_t smA[16384];
    int tid = threadIdx.x;
    int warp = tid >> 5, lane = tid & 31;
    int gid = lane >> 2, tig = lane & 3;
    int rowBase = blockIdx.x * 128;
    uint32_t smA_b = smem_u32(smA);

    // per-thread A-fill geometry (constant across chunks)
    int rowA[4], chA[4], stoff[4];
    bool inb[4];
#pragma unroll
    for (int j = 0; j < 4; j++) {
        int c = tid + 256 * j;
        rowA[j] = c >> 3; chA[j] = c & 7;
        stoff[j] = rowA[j] * 128 + ((chA[j] ^ (rowA[j] & 7)) << 4);
        inb[j] = (rowBase + rowA[j]) < N;
    }

    float acc[8][4];
#pragma unroll
    for (int g = 0; g < 8; g++)
#pragma unroll
        for (int j = 0; j < 4; j++) acc[g][j] = 0.f;

    uint4 v[4];
    // prologue: load chunk 0
#pragma unroll
    for (int j = 0; j < 4; j++) {
        v[j] = make_uint4(0u, 0u, 0u, 0u);
        if (inb[j])
            v[j] = *(const uint4*)(g_Sb + (rowBase + rowA[j]) * 400 + chA[j] * 4);
    }

    for (int c0 = 0; c0 < 14; c0++) {
#pragma unroll
        for (int j = 0; j < 4; j++) *(uint4*)(smA + stoff[j]) = v[j];
        __syncthreads();
        // prefetch next chunk while MMAs run
        if (c0 < 13) {
            int cn = c0 + 1;
#pragma unroll
            for (int j = 0; j < 4; j++) {
                v[j] = make_uint4(0u, 0u, 0u, 0u);
                if (inb[j]) {
                    if (cn < 13) {
                        int off = cn * 32 + chA[j] * 4;
                        if (off < 400)
                            v[j] = *(const uint4*)(g_Sb + (rowBase + rowA[j]) * 400 + off);
                    } else if (chA[j] < 4) {
                        v[j] = *(const uint4*)(g_h1b + (rowBase + rowA[j]) * 16 + chA[j] * 4);
                    }
                }
            }
        }
#pragma unroll
        for (int ks = 0; ks < 4; ks++) {
            int mrow = warp * 16 + (lane & 15);
            uint32_t addr = smA_b + mrow * 128 + (((ks * 2 + (lane >> 4)) ^ (mrow & 7)) << 4);
            uint32_t a0, a1, a2, a3;
            ldmatrix_x4(a0, a1, a2, a3, addr);
            int sg = c0 * 4 + ks;
            const uint2* bf = g_W2f + (sg << 8) + lane;
#pragma unroll
            for (int ng = 0; ng < 8; ng++) {
                uint2 b = bf[ng << 5];
                mma_bf16(acc[ng], a0, a1, a2, a3, b.x, b.y);
            }
        }
        __syncthreads();
    }

    int r0 = rowBase + warp * 16 + gid;
    int r1 = r0 + 8;
    int bt0 = (r0 < N) ? batch[r0] : -1;
    int bt1 = (r1 < N) ? batch[r1] : -1;
#pragma unroll
    for (int ng = 0; ng < 8; ng++) {
        int col = ng * 8 + tig * 2;
        float2 bb = *(const float2*)(b2 + col);
        if (bt0 >= 0) {
            red_f32(g_pool + bt0 * C2 + col,     fmaxf(acc[ng][0] + bb.x, 0.f));
            red_f32(g_pool + bt0 * C2 + col + 1, fmaxf(acc[ng][1] + bb.y, 0.f));
        }
        if (bt1 >= 0) {
            red_f32(g_pool + bt1 * C2 + col,     fmaxf(acc[ng][2] + bb.x, 0.f));
            red_f32(g_pool + bt1 * C2 + col + 1, fmaxf(acc[ng][3] + bb.y, 0.f));
        }
    }
}

// ---------------- head MLP + log_softmax (cnt via binary search on sorted batch) ----------------
__global__ void k_mlp(const float* __restrict__ Wf1, const float* __restrict__ bf1,
                      const float* __restrict__ Wf2, const float* __restrict__ bf2,
                      const int* __restrict__ batch, int N,
                      float* __restrict__ out) {
    int b = blockIdx.x;
    int j = threadIdx.x;
    __shared__ float gs[C2];
    __shared__ float ts[128];
    __shared__ float lg[10];
    __shared__ float s_cinv;
    if (j == 0) {
        int lo = 0, hi = N;
        while (lo < hi) { int m = (lo + hi) >> 1; if (batch[m] < b) lo = m + 1; else hi = m; }
        int lo2 = lo; hi = N;
        while (lo2 < hi) { int m = (lo2 + hi) >> 1; if (batch[m] < b + 1) lo2 = m + 1; else hi = m; }
        s_cinv = 1.f / fmaxf((float)(lo2 - lo), 1.f);
    }
    __syncthreads();
    if (j < C2) gs[j] = g_pool[b * C2 + j] * s_cinv;
    __syncthreads();
    float t = bf1[j];
#pragma unroll
    for (int k = 0; k < C2; k++) t += gs[k] * Wf1[k * 128 + j];
    ts[j] = fmaxf(t, 0.f);
    __syncthreads();
    if (j < 10) {
        float a = bf2[j];
#pragma unroll
        for (int q = 0; q < 128; q++) a += ts[q] * Wf2[q * 10 + j];
        lg[j] = a;
    }
    __syncthreads();
    if (j == 0) {
        float m = lg[0];
#pragma unroll
        for (int q = 1; q < 10; q++) m = fmaxf(m, lg[q]);
        float s = 0.f;
#pragma unroll
        for (int q = 0; q < 10; q++) s += expf(lg[q] - m);
        float l = logf(s) + m;
#pragma unroll
        for (int q = 0; q < 10; q++) out[b * 10 + q] = lg[q] - l;
    }
}

// ---------------- launch ----------------
extern "C" void kernel_launch(void* const* d_in, const int* in_sizes, int n_in,
                              void* d_out, int out_size) {
    const float* x     = (const float*)d_in[0];
    const float* ea    = (const float*)d_in[1];
    const float* W1    = (const float*)d_in[2];
    const float* root1 = (const float*)d_in[3];
    const float* b1    = (const float*)d_in[4];
    const float* W2    = (const float*)d_in[5];
    const float* root2 = (const float*)d_in[6];
    const float* b2    = (const float*)d_in[7];
    const float* Wf1   = (const float*)d_in[8];
    const float* bf1   = (const float*)d_in[9];
    const float* Wf2   = (const float*)d_in[10];
    const float* bf2   = (const float*)d_in[11];
    const int*   ei    = (const int*)d_in[12];
    const int*   batch = (const int*)d_in[13];

    int N = in_sizes[0];
    int E = in_sizes[1] / 2;
    const int* src = ei;
    const int* dst = ei + E;
    float* out = (float*)d_out;

    k_zero_prep<<<2048, 256>>>(W2, root2, N);
    k_edge1<<<(E + 255) / 256, 256>>>(x, ea, src, dst, E);
    k_h1<<<(N * 16 + 255) / 256, 256>>>(x, W1, root1, b1, N);
    k_edge2<<<(E * 16 + 255) / 256, 256>>>(src, dst, E);
    k_gemm_mma<<<(N + 127) / 128, 256>>>(b2, batch, N);
    k_mlp<<<NG, 128>>>(Wf1, bf1, Wf2, bf2, batch, N, out);
}